// round 14
// baseline (speedup 1.0000x reference)
#include <cuda_runtime.h>
#include <cuda_bf16.h>
#include <cuda_fp16.h>
#include <cstdint>

#define NDIM 512
#define DDIM 128
#define NN (NDIM*NDIM)

// Scratch (allocation-free rule: __device__ globals)
__device__ __half g_L16[(size_t)DDIM * NN];    // [c][i][k] fp16
__device__ __half g_R16[(size_t)DDIM * NN];    // [c][j][k] fp16
__device__ float g_T[(size_t)DDIM * NN];       // [c][i][j]
// fp16 weights for stage-1 (prepped by k0): lrp split hi/lo, gate single
__device__ __half g_Wl_h16[256 * 128];
__device__ __half g_Wl_l16[256 * 128];
__device__ __half g_Wg_16 [256 * 128];
// fp16 weights for stage-2 (og / op)
__device__ __half g_Wo_16[128 * 128];
__device__ __half g_Wp_16[128 * 128];

__device__ __forceinline__ float sigmoidf_(float x) {
    return 1.0f / (1.0f + __expf(-x));
}

__device__ __forceinline__ uint32_t smem_u32(const void* p) {
    uint32_t a;
    asm("{ .reg .u64 t; cvta.to.shared.u64 t, %1; cvt.u32.u64 %0, t; }" : "=r"(a) : "l"(p));
    return a;
}

__device__ __forceinline__ uint32_t sw128(uint32_t bo) {
    return bo ^ ((bo >> 3) & 0x70);
}

__device__ __forceinline__ void cp16(uint32_t dst, const void* src) {
    asm volatile("cp.async.cg.shared.global [%0], [%1], 16;" :: "r"(dst), "l"(src) : "memory");
}
#define CP_COMMIT() asm volatile("cp.async.commit_group;" ::: "memory")
#define CP_WAIT0()  asm volatile("cp.async.wait_group 0;" ::: "memory")
#define CP_WAIT1()  asm volatile("cp.async.wait_group 1;" ::: "memory")

__device__ __forceinline__ void ldm_x4(uint32_t r[4], uint32_t addr) {
    asm volatile("ldmatrix.sync.aligned.m8n8.x4.shared.b16 {%0,%1,%2,%3}, [%4];"
        : "=r"(r[0]), "=r"(r[1]), "=r"(r[2]), "=r"(r[3]) : "r"(addr));
}

// fp16 MMA (all kernels)
__device__ __forceinline__ void mma16816h(float c[4], const uint32_t a[4],
                                          uint32_t b0, uint32_t b1) {
    asm volatile("mma.sync.aligned.m16n8k16.row.col.f32.f16.f16.f32 "
        "{%0,%1,%2,%3}, {%4,%5,%6,%7}, {%8,%9}, {%0,%1,%2,%3};"
        : "+f"(c[0]), "+f"(c[1]), "+f"(c[2]), "+f"(c[3])
        : "r"(a[0]), "r"(a[1]), "r"(a[2]), "r"(a[3]), "r"(b0), "r"(b1));
}

// single fp16 pack (bits in low 16)
__device__ __forceinline__ uint32_t pack_h1(float v) {
    __half h = __float2half(v);
    return (uint32_t)*reinterpret_cast<unsigned short*>(&h);
}

__device__ __forceinline__ uint32_t pack_h2(float a, float b) {
    __half2 h = __floats2half2_rn(a, b);
    return *reinterpret_cast<uint32_t*>(&h);
}

// ---------------------------------------------------------------------------
// Kernel 0: weight prep (fp16 split lrp, fp16 gate/og/op)
// ---------------------------------------------------------------------------
__global__ void k0_wprep(const float* __restrict__ lrpw, const float* __restrict__ gatew,
                         const float* __restrict__ ogw,  const float* __restrict__ opw)
{
    int i = blockIdx.x * blockDim.x + threadIdx.x;
    if (i < 256 * 128) {
        float v = lrpw[i];
        __half h = __float2half(v);
        g_Wl_h16[i] = h;
        g_Wl_l16[i] = __float2half(v - __half2float(h));
        g_Wg_16[i] = __float2half(gatew[i]);
    }
    if (i < 128 * 128) {
        g_Wo_16[i] = __float2half(ogw[i]);
        g_Wp_16[i] = __float2half(opw[i]);
    }
}

// ---------------------------------------------------------------------------
// Kernel 1 (fp16 HMMA): LN1 + lrp (2-prod) / gate (1-prod) -> fp16 L / R
// 32-channel c-tiles (8 tiles). smem: A 32KB | W 24KB (stage 16.9K aliases W)
// 56KB -> 3 CTAs/SM
// ---------------------------------------------------------------------------
#define K1_A_OFF   0
#define K1_W_OFF   32768
#define K1_SMEM    57344

__global__ __launch_bounds__(256, 3)
void k1_mma(const float* __restrict__ Z, const float* __restrict__ mask,
            const float* __restrict__ ln1w, const float* __restrict__ ln1b,
            const float* __restrict__ lrpb, const float* __restrict__ gateb)
{
    extern __shared__ __align__(1024) char smc[];
    const uint32_t sbase = smem_u32(smc);
    uint32_t* stage = reinterpret_cast<uint32_t*>(smc + K1_W_OFF);   // aliases W planes

    const int tid = threadIdx.x;
    const int warp = tid >> 5;
    const uint32_t lane = tid & 31;
    const int r0 = blockIdx.x * 128;

    // ---- Phase A: load Z rows, LN1, single fp16 plane (2 k-chunks) ----
    {
        const int k4 = lane * 4;
        const int kc = lane >> 4;
        const uint32_t kb = (lane & 15) * 8;
        float4 w4 = *reinterpret_cast<const float4*>(ln1w + k4);
        float4 b4 = *reinterpret_cast<const float4*>(ln1b + k4);
        #pragma unroll 2
        for (int rr = 0; rr < 16; rr++) {
            int rloc = warp * 16 + rr;
            float4 v = *reinterpret_cast<const float4*>(Z + (size_t)(r0 + rloc) * DDIM + k4);
            float s  = v.x + v.y + v.z + v.w;
            float s2 = v.x * v.x + v.y * v.y + v.z * v.z + v.w * v.w;
            #pragma unroll
            for (int o = 16; o; o >>= 1) {
                s  += __shfl_xor_sync(0xffffffffu, s, o);
                s2 += __shfl_xor_sync(0xffffffffu, s2, o);
            }
            float m = s * 0.0078125f;
            float var = fmaf(-m, m, s2 * 0.0078125f);
            float rstd = rsqrtf(var + 1e-5f);
            float zn[4] = {
                (v.x - m) * rstd * w4.x + b4.x,
                (v.y - m) * rstd * w4.y + b4.y,
                (v.z - m) * rstd * w4.z + b4.z,
                (v.w - m) * rstd * w4.w + b4.w };
            uint32_t sw = sw128((uint32_t)(rloc * 128) + kb);
            *reinterpret_cast<uint2*>(smc + K1_A_OFF + kc * 16384 + sw) =
                make_uint2(pack_h2(zn[0], zn[1]), pack_h2(zn[2], zn[3]));
        }
    }
    __syncthreads();

    const int wm = (warp >> 1) * 32;     // 0..96
    const int wn = (warp & 1) * 16;      // 0/16 within 32-channel tile

    const uint32_t a_row = (lane & 7) + ((lane >> 3) & 1) * 8;
    const uint32_t a_kb  = (lane >> 4) * 16;
    const uint32_t b_row = (lane & 7) + ((lane >> 4) & 1) * 8;
    const uint32_t b_kb  = ((lane >> 3) & 1) * 16;

    const __half* wtab[3] = { g_Wl_h16, g_Wl_l16, g_Wg_16 };

    #pragma unroll 1
    for (int ct = 0; ct < 8; ct++) {
        const int cbase = ct * 32;

        // ---- load 6 W planes (3 mats x 2 kc), 32 rows x 128B each ----
        #pragma unroll
        for (int it = 0; it < 6; it++) {
            int u = it * 256 + tid;
            int p = u >> 8; int idx = u & 255;
            int row = idx >> 3, q = idx & 7;
            int shl = p >> 1, kc = p & 1;
            const __half* src = wtab[shl] + (size_t)(cbase + row) * 128 + kc * 64 + q * 8;
            cp16(sbase + K1_W_OFF + p * 4096 + sw128((uint32_t)(row * 128 + q * 16)), src);
        }
        CP_COMMIT();
        CP_WAIT0();
        __syncthreads();

        float accl[2][2][4], accg[2][2][4];
        #pragma unroll
        for (int mt = 0; mt < 2; mt++)
            #pragma unroll
            for (int nt = 0; nt < 2; nt++)
                #pragma unroll
                for (int q = 0; q < 4; q++) { accl[mt][nt][q] = 0.f; accg[mt][nt][q] = 0.f; }

        #pragma unroll
        for (int kc = 0; kc < 2; kc++) {
            #pragma unroll
            for (int ks = 0; ks < 4; ks++) {
                uint32_t kb = ks * 32;
                uint32_t a[2][4];
                #pragma unroll
                for (int mt = 0; mt < 2; mt++) {
                    uint32_t sw = sw128((uint32_t)((wm + mt * 16 + a_row) * 128) + kb + a_kb);
                    ldm_x4(a[mt], sbase + K1_A_OFF + kc * 16384 + sw);
                }
                uint32_t swb = sw128((uint32_t)((wn + b_row) * 128) + kb + b_kb);
                uint32_t wlh[4], wll[4], wg[4];
                ldm_x4(wlh, sbase + K1_W_OFF + (0 + kc) * 4096 + swb);
                ldm_x4(wll, sbase + K1_W_OFF + (2 + kc) * 4096 + swb);
                ldm_x4(wg,  sbase + K1_W_OFF + (4 + kc) * 4096 + swb);
                #pragma unroll
                for (int mt = 0; mt < 2; mt++) {
                    #pragma unroll
                    for (int h = 0; h < 2; h++) {
                        float* cl = accl[mt][h];
                        float* cg = accg[mt][h];
                        mma16816h(cl, a[mt], wlh[h*2], wlh[h*2+1]);
                        mma16816h(cl, a[mt], wll[h*2], wll[h*2+1]);
                        mma16816h(cg, a[mt], wg[h*2],  wg[h*2+1]);
                    }
                }
            }
        }
        __syncthreads();   // all warps done reading W before stage (aliased) writes

        #pragma unroll
        for (int mt = 0; mt < 2; mt++) {
            int rl0 = wm + mt * 16 + (int)(lane >> 2);
            float m0 = mask[r0 + rl0];
            float m1 = mask[r0 + rl0 + 8];
            #pragma unroll
            for (int nt = 0; nt < 2; nt++) {
                int cl0 = wn + nt * 8 + 2 * (int)(lane & 3);
                float lb0 = lrpb[cbase + cl0],  lb1 = lrpb[cbase + cl0 + 1];
                float gb0 = gateb[cbase + cl0], gb1 = gateb[cbase + cl0 + 1];
                float* vl = accl[mt][nt];
                float* vg = accg[mt][nt];
                stage[(cl0    ) * 132 + rl0    ] = pack_h1((vl[0] + lb0) * m0 * sigmoidf_(vg[0] + gb0));
                stage[(cl0 + 1) * 132 + rl0    ] = pack_h1((vl[1] + lb1) * m0 * sigmoidf_(vg[1] + gb1));
                stage[(cl0    ) * 132 + rl0 + 8] = pack_h1((vl[2] + lb0) * m1 * sigmoidf_(vg[2] + gb0));
                stage[(cl0 + 1) * 132 + rl0 + 8] = pack_h1((vl[3] + lb1) * m1 * sigmoidf_(vg[3] + gb1));
            }
        }
        __syncthreads();

        {
            int c_loc = tid >> 3;            // 0..31
            int seg = tid & 7;               // 8 segments of 16 rows
            int cg = cbase + c_loc;
            __half* dst = (cg < 128) ? (g_L16 + (size_t)cg * NN) : (g_R16 + (size_t)(cg - 128) * NN);
            int rb = seg * 16;
            const uint32_t* srow = &stage[c_loc * 132 + rb];
            #pragma unroll
            for (int blk = 0; blk < 2; blk++) {
                uint32_t hw[4];
                #pragma unroll
                for (int q = 0; q < 4; q++) {
                    uint32_t p0 = srow[blk * 8 + q * 2];
                    uint32_t p1 = srow[blk * 8 + q * 2 + 1];
                    hw[q] = (p0 & 0xffffu) | (p1 << 16);
                }
                *reinterpret_cast<uint4*>(dst + r0 + rb + blk * 8) = make_uint4(hw[0], hw[1], hw[2], hw[3]);
            }
        }
        __syncthreads();
    }
}

// ---------------------------------------------------------------------------
// Kernel 2: fp16 1-product mma.sync GEMM  T_c = L_c @ R_c^T
// CTA tile 128(i) x 64(j), K-chunk 64, 3-stage, 3 CTAs/SM.
// ---------------------------------------------------------------------------
#define K2_AP 16384
#define K2_BP 8192
#define K2_STG (K2_AP + K2_BP)       // 24576
#define K2_SMEM (3 * K2_STG)         // 73728

__device__ __forceinline__ void k2_prefetch(uint32_t sbase, int stage_i,
    const __half* A, const __half* B,
    int i0, int j0, int k0, int tid)
{
    uint32_t st = sbase + stage_i * K2_STG;
    #pragma unroll
    for (int it = 0; it < 4; it++) {
        int idx = it * 256 + tid;
        int r = idx >> 3, q = idx & 7;
        uint32_t sw = sw128((uint32_t)(r * 128 + q * 16));
        cp16(st + sw, A + (size_t)(i0 + r) * NDIM + k0 + q * 8);
    }
    #pragma unroll
    for (int it = 0; it < 2; it++) {
        int idx = it * 256 + tid;
        int r = idx >> 3, q = idx & 7;
        uint32_t sw = sw128((uint32_t)(r * 128 + q * 16));
        cp16(st + K2_AP + sw, B + (size_t)(j0 + r) * NDIM + k0 + q * 8);
    }
    CP_COMMIT();
}

__global__ __launch_bounds__(256, 3)
void k2_tri_mma()
{
    extern __shared__ __align__(1024) char smc[];
    const uint32_t sbase = smem_u32(smc);
    const int tid = threadIdx.x;
    const int warp = tid >> 5;
    const uint32_t lane = tid & 31;
    const int c = blockIdx.z;
    const int i0 = blockIdx.x * 128, j0 = blockIdx.y * 64;

    const __half* __restrict__ A = g_L16 + (size_t)c * NN;
    const __half* __restrict__ B = g_R16 + (size_t)c * NN;
    float* __restrict__ Tc = g_T + (size_t)c * NN;

    const int wm = (warp >> 1) * 32;
    const int wn = (warp & 1) * 32;

    const uint32_t a_row = (lane & 7) + ((lane >> 3) & 1) * 8;
    const uint32_t a_kb  = (lane >> 4) * 16;
    const uint32_t b_row = (lane & 7) + ((lane >> 4) & 1) * 8;
    const uint32_t b_kb  = ((lane >> 3) & 1) * 16;

    float acc[2][4][4];
    #pragma unroll
    for (int mt = 0; mt < 2; mt++)
        #pragma unroll
        for (int nt = 0; nt < 4; nt++)
            #pragma unroll
            for (int q = 0; q < 4; q++) acc[mt][nt][q] = 0.0f;

    k2_prefetch(sbase, 0, A, B, i0, j0, 0, tid);
    k2_prefetch(sbase, 1, A, B, i0, j0, 64, tid);

    #pragma unroll 1
    for (int ch = 0; ch < 8; ch++) {
        if (ch == 7) { CP_WAIT0(); } else { CP_WAIT1(); }
        __syncthreads();
        if (ch + 2 < 8)
            k2_prefetch(sbase, (ch + 2) % 3, A, B, i0, j0, (ch + 2) * 64, tid);

        uint32_t st = sbase + (ch % 3) * K2_STG;
        uint32_t sA = st, sB = st + K2_AP;

        #pragma unroll
        for (int ks = 0; ks < 4; ks++) {
            uint32_t kb = ks * 32;
            uint32_t a[2][4];
            #pragma unroll
            for (int mt = 0; mt < 2; mt++) {
                uint32_t sw = sw128((uint32_t)((wm + mt * 16 + a_row) * 128) + kb + a_kb);
                ldm_x4(a[mt], sA + sw);
            }
            #pragma unroll
            for (int ng = 0; ng < 2; ng++) {
                uint32_t sw = sw128((uint32_t)((wn + ng * 16 + b_row) * 128) + kb + b_kb);
                uint32_t b[4];
                ldm_x4(b, sB + sw);
                #pragma unroll
                for (int mt = 0; mt < 2; mt++) {
                    #pragma unroll
                    for (int h = 0; h < 2; h++) {
                        mma16816h(acc[mt][ng * 2 + h], a[mt], b[h * 2], b[h * 2 + 1]);
                    }
                }
            }
        }
        __syncthreads();
    }

    const int rbase = i0 + wm + (int)(lane >> 2);
    const int cbase = j0 + wn + 2 * (int)(lane & 3);
    #pragma unroll
    for (int mt = 0; mt < 2; mt++) {
        #pragma unroll
        for (int nt = 0; nt < 4; nt++) {
            float* cc = acc[mt][nt];
            int col = cbase + nt * 8;
            int r1 = rbase + mt * 16;
            *reinterpret_cast<float2*>(&Tc[(size_t)r1 * NDIM + col])       = make_float2(cc[0], cc[1]);
            *reinterpret_cast<float2*>(&Tc[(size_t)(r1 + 8) * NDIM + col]) = make_float2(cc[2], cc[3]);
        }
    }
}

// ---------------------------------------------------------------------------
// Kernel 3 (fp16 HMMA): 64 rows x 128 cols, tri kept as fp16 swizzled plane
// (serves as LN input + gate-A operand + residual). 3 CTAs/SM.
// smem: TRI 16KB | ZN 16KB | W 32KB = 64KB
// ---------------------------------------------------------------------------
#define K3_TRI_OFF 0
#define K3_ZN_OFF  16384
#define K3_W_OFF   32768
#define K3_SMEM    65536

__device__ __forceinline__ void k3_loadW(uint32_t sbase, int ch0, int tid) {
    #pragma unroll
    for (int it = 0; it < 8; it++) {
        int u = it * 256 + tid;
        int p = u >> 9; int idx = u & 511;
        int row = idx >> 3, q = idx & 7;
        int pl = p >> 1, kc = p & 1;
        const __half* src = (pl == 0 ? g_Wo_16 : g_Wp_16) + (size_t)(ch0 + row) * 128 + kc * 64 + q * 8;
        cp16(sbase + K3_W_OFF + p * 8192 + sw128((uint32_t)(row * 128 + q * 16)), src);
    }
    CP_COMMIT();
}

__global__ __launch_bounds__(256, 3)
void k3_mma(const float* __restrict__ ogb, const float* __restrict__ ln2w,
            const float* __restrict__ ln2b, const float* __restrict__ outb,
            float* __restrict__ out)
{
    extern __shared__ __align__(1024) char smc[];
    const uint32_t sbase = smem_u32(smc);

    const int tid = threadIdx.x;
    const int warp = tid >> 5;
    const uint32_t lane = tid & 31;
    const int r0 = blockIdx.x * 64;

    k3_loadW(sbase, 0, tid);

    // ---- gather g_T [c][r] -> TRI plane fp16 swizzled [kc][row][128B] ----
    #pragma unroll
    for (int it = 0; it < 8; it++) {
        int u = it * 256 + tid;
        int cch = u >> 4;                 // 0..127
        int q = u & 15;                   // float4 chunk over 64 rows
        float4 v = *reinterpret_cast<const float4*>(g_T + (size_t)cch * NN + r0 + q * 4);
        int kc = cch >> 6;
        uint32_t cb = (uint32_t)(cch & 63) * 2;
        char* pl = smc + K3_TRI_OFF + kc * 8192;
        *reinterpret_cast<__half*>(pl + sw128((uint32_t)((q * 4 + 0) * 128) + cb)) = __float2half(v.x);
        *reinterpret_cast<__half*>(pl + sw128((uint32_t)((q * 4 + 1) * 128) + cb)) = __float2half(v.y);
        *reinterpret_cast<__half*>(pl + sw128((uint32_t)((q * 4 + 2) * 128) + cb)) = __float2half(v.z);
        *reinterpret_cast<__half*>(pl + sw128((uint32_t)((q * 4 + 3) * 128) + cb)) = __float2half(v.w);
    }
    __syncthreads();

    // ---- LN2 per row (8 rows/warp) from TRI plane; emit ZN fp16 plane ----
    {
        const int c4 = lane * 4;
        const int kc = lane >> 4;
        const uint32_t kb = (lane & 15) * 8;
        float4 w4 = *reinterpret_cast<const float4*>(ln2w + c4);
        float4 b4 = *reinterpret_cast<const float4*>(ln2b + c4);
        #pragma unroll 1
        for (int rr = 0; rr < 8; rr++) {
            int rloc = warp * 8 + rr;
            uint32_t sw = sw128((uint32_t)(rloc * 128) + kb);
            uint2 t2 = *reinterpret_cast<uint2*>(smc + K3_TRI_OFF + kc * 8192 + sw);
            float2 p0 = __half22float2(*reinterpret_cast<__half2*>(&t2.x));
            float2 p1 = __half22float2(*reinterpret_cast<__half2*>(&t2.y));
            float s  = p0.x + p0.y + p1.x + p1.y;
            float s2 = p0.x * p0.x + p0.y * p0.y + p1.x * p1.x + p1.y * p1.y;
            #pragma unroll
            for (int o = 16; o; o >>= 1) {
                s  += __shfl_xor_sync(0xffffffffu, s, o);
                s2 += __shfl_xor_sync(0xffffffffu, s2, o);
            }
            float m = s * 0.0078125f;
            float var = fmaf(-m, m, s2 * 0.0078125f);
            float rstd = rsqrtf(var + 1e-5f);
            float zn0 = (p0.x - m) * rstd * w4.x + b4.x;
            float zn1 = (p0.y - m) * rstd * w4.y + b4.y;
            float zn2 = (p1.x - m) * rstd * w4.z + b4.z;
            float zn3 = (p1.y - m) * rstd * w4.w + b4.w;
            *reinterpret_cast<uint2*>(smc + K3_ZN_OFF + kc * 8192 + sw) =
                make_uint2(pack_h2(zn0, zn1), pack_h2(zn2, zn3));
        }
    }

    const int wm = (warp >> 1) * 16;
    const int wn = (warp & 1) * 32;

    const uint32_t a_row = (lane & 7) + ((lane >> 3) & 1) * 8;
    const uint32_t a_kb  = (lane >> 4) * 16;
    const uint32_t b_row = (lane & 7) + ((lane >> 4) & 1) * 8;
    const uint32_t b_kb  = ((lane >> 3) & 1) * 16;

    #pragma unroll 1
    for (int hh = 0; hh < 2; hh++) {
        const int ch0 = hh * 64;
        CP_WAIT0();
        __syncthreads();

        float accg[4][4], accz[4][4];
        #pragma unroll
        for (int nt = 0; nt < 4; nt++)
            #pragma unroll
            for (int q = 0; q < 4; q++) { accg[nt][q] = 0.f; accz[nt][q] = 0.f; }

        #pragma unroll
        for (int kc = 0; kc < 2; kc++) {
            #pragma unroll
            for (int ks = 0; ks < 4; ks++) {
                uint32_t kb = ks * 32;
                uint32_t ag[4], az[4];
                uint32_t swa = sw128((uint32_t)((wm + a_row) * 128) + kb + a_kb);
                ldm_x4(ag, sbase + K3_TRI_OFF + kc * 8192 + swa);
                ldm_x4(az, sbase + K3_ZN_OFF  + kc * 8192 + swa);
                #pragma unroll
                for (int ng = 0; ng < 2; ng++) {
                    uint32_t swb = sw128((uint32_t)((wn + ng * 16 + b_row) * 128) + kb + b_kb);
                    uint32_t wo[4], wp[4];
                    ldm_x4(wo, sbase + K3_W_OFF + (0*2 + kc) * 8192 + swb);
                    ldm_x4(wp, sbase + K3_W_OFF + (1*2 + kc) * 8192 + swb);
                    #pragma unroll
                    for (int h = 0; h < 2; h++) {
                        mma16816h(accg[ng * 2 + h], ag, wo[h*2], wo[h*2+1]);
                        mma16816h(accz[ng * 2 + h], az, wp[h*2], wp[h*2+1]);
                    }
                }
            }
        }
        __syncthreads();
        if (hh == 0) k3_loadW(sbase, 64, tid);

        // ---- epilogue: out = tri(fp16) + sigmoid(accg+ogb)*(accz+outb) ----
        {
            int rl0 = wm + (int)(lane >> 2);
            char* triP = smc + K3_TRI_OFF + hh * 8192;
            #pragma unroll
            for (int nt = 0; nt < 4; nt++) {
                int dl = wn + nt * 8 + 2 * (int)(lane & 3);
                int d = ch0 + dl;
                float ob0 = ogb[d],  ob1 = ogb[d + 1];
                float ub0 = outb[d], ub1 = outb[d + 1];
                float* cg = accg[nt];
                float* cz = accz[nt];
                uint32_t tb0 = *reinterpret_cast<uint32_t*>(triP + sw128((uint32_t)(rl0 * 128) + dl * 2));
                uint32_t tb1 = *reinterpret_cast<uint32_t*>(triP + sw128((uint32_t)((rl0 + 8) * 128) + dl * 2));
                float2 t0 = __half22float2(*reinterpret_cast<__half2*>(&tb0));
                float2 t1 = __half22float2(*reinterpret_cast<__half2*>(&tb1));
                float2 o0, o1;
                o0.x = t0.x + sigmoidf_(cg[0] + ob0) * (cz[0] + ub0);
                o0.y = t0.y + sigmoidf_(cg[1] + ob1) * (cz[1] + ub1);
                o1.x = t1.x + sigmoidf_(cg[2] + ob0) * (cz[2] + ub0);
                o1.y = t1.y + sigmoidf_(cg[3] + ob1) * (cz[3] + ub1);
                *reinterpret_cast<float2*>(&out[(size_t)(r0 + rl0) * DDIM + d])     = o0;
                *reinterpret_cast<float2*>(&out[(size_t)(r0 + rl0 + 8) * DDIM + d]) = o1;
            }
        }
    }
}

// ---------------------------------------------------------------------------
extern "C" void kernel_launch(void* const* d_in, const int* in_sizes, int n_in,
                              void* d_out, int out_size)
{
    const float* Z     = (const float*)d_in[0];
    const float* mask  = (const float*)d_in[1];
    const float* ln1w  = (const float*)d_in[2];
    const float* ln1b  = (const float*)d_in[3];
    const float* lrpw  = (const float*)d_in[4];
    const float* lrpb  = (const float*)d_in[5];
    const float* gatew = (const float*)d_in[6];
    const float* gateb = (const float*)d_in[7];
    const float* ogw   = (const float*)d_in[8];
    const float* ogb   = (const float*)d_in[9];
    const float* ln2w  = (const float*)d_in[10];
    const float* ln2b  = (const float*)d_in[11];
    const float* opw   = (const float*)d_in[12];
    const float* outb  = (const float*)d_in[13];
    float* out = (float*)d_out;

    cudaFuncSetAttribute(k1_mma,     cudaFuncAttributeMaxDynamicSharedMemorySize, K1_SMEM);
    cudaFuncSetAttribute(k2_tri_mma, cudaFuncAttributeMaxDynamicSharedMemorySize, K2_SMEM);
    cudaFuncSetAttribute(k3_mma,     cudaFuncAttributeMaxDynamicSharedMemorySize, K3_SMEM);

    k0_wprep<<<128, 256>>>(lrpw, gatew, ogw, opw);

    k1_mma<<<NN / 128, 256, K1_SMEM>>>(Z, mask, ln1w, ln1b, lrpb, gateb);

    dim3 g2(4, 8, 128);
    k2_tri_mma<<<g2, 256, K2_SMEM>>>();

    k3_mma<<<NN / 64, 256, K3_SMEM>>>(ogb, ln2w, ln2b, outb, out);
}

// round 17
// speedup vs baseline: 1.6268x; 1.6268x over previous
#include <cuda_runtime.h>
#include <cuda_bf16.h>
#include <cuda_fp16.h>
#include <cstdint>

#define NDIM 512
#define DDIM 128
#define NN (NDIM*NDIM)

// Scratch (allocation-free rule: __device__ globals)
__device__ __half g_L16[(size_t)DDIM * NN];    // [c][i][k] fp16
__device__ __half g_R16[(size_t)DDIM * NN];    // [c][j][k] fp16
__device__ float g_T[(size_t)DDIM * NN];       // [c][i][j]
// fp16 weights for stage-1 (prepped by k0): lrp split hi/lo, gate single
__device__ __half g_Wl_h16[256 * 128];
__device__ __half g_Wl_l16[256 * 128];
__device__ __half g_Wg_16 [256 * 128];
// bf16 weights for stage-2 (og / op)
__device__ __nv_bfloat16 g_Wo_bf[128 * 128];
__device__ __nv_bfloat16 g_Wp_bf[128 * 128];

__device__ __forceinline__ float sigmoidf_(float x) {
    return 1.0f / (1.0f + __expf(-x));
}

__device__ __forceinline__ uint32_t smem_u32(const void* p) {
    uint32_t a;
    asm("{ .reg .u64 t; cvta.to.shared.u64 t, %1; cvt.u32.u64 %0, t; }" : "=r"(a) : "l"(p));
    return a;
}

__device__ __forceinline__ uint32_t sw128(uint32_t bo) {
    return bo ^ ((bo >> 3) & 0x70);
}

__device__ __forceinline__ void cp16(uint32_t dst, const void* src) {
    asm volatile("cp.async.cg.shared.global [%0], [%1], 16;" :: "r"(dst), "l"(src) : "memory");
}
#define CP_COMMIT() asm volatile("cp.async.commit_group;" ::: "memory")
#define CP_WAIT0()  asm volatile("cp.async.wait_group 0;" ::: "memory")
#define CP_WAIT1()  asm volatile("cp.async.wait_group 1;" ::: "memory")

__device__ __forceinline__ void ldm_x4(uint32_t r[4], uint32_t addr) {
    asm volatile("ldmatrix.sync.aligned.m8n8.x4.shared.b16 {%0,%1,%2,%3}, [%4];"
        : "=r"(r[0]), "=r"(r[1]), "=r"(r[2]), "=r"(r[3]) : "r"(addr));
}

// bf16 MMA (k3)
__device__ __forceinline__ void mma16816(float c[4], const uint32_t a[4],
                                         uint32_t b0, uint32_t b1) {
    asm volatile("mma.sync.aligned.m16n8k16.row.col.f32.bf16.bf16.f32 "
        "{%0,%1,%2,%3}, {%4,%5,%6,%7}, {%8,%9}, {%0,%1,%2,%3};"
        : "+f"(c[0]), "+f"(c[1]), "+f"(c[2]), "+f"(c[3])
        : "r"(a[0]), "r"(a[1]), "r"(a[2]), "r"(a[3]), "r"(b0), "r"(b1));
}

// fp16 MMA (k1/k2)
__device__ __forceinline__ void mma16816h(float c[4], const uint32_t a[4],
                                          uint32_t b0, uint32_t b1) {
    asm volatile("mma.sync.aligned.m16n8k16.row.col.f32.f16.f16.f32 "
        "{%0,%1,%2,%3}, {%4,%5,%6,%7}, {%8,%9}, {%0,%1,%2,%3};"
        : "+f"(c[0]), "+f"(c[1]), "+f"(c[2]), "+f"(c[3])
        : "r"(a[0]), "r"(a[1]), "r"(a[2]), "r"(a[3]), "r"(b0), "r"(b1));
}

// single fp16 pack (bits in low 16)
__device__ __forceinline__ uint32_t pack_h1(float v) {
    __half h = __float2half(v);
    return (uint32_t)*reinterpret_cast<unsigned short*>(&h);
}

__device__ __forceinline__ uint32_t pack_h2(float a, float b) {
    __half2 h = __floats2half2_rn(a, b);
    return *reinterpret_cast<uint32_t*>(&h);
}

__device__ __forceinline__ uint32_t pack_bf2(float a, float b) {
    __nv_bfloat16 h0 = __float2bfloat16(a);
    __nv_bfloat16 h1 = __float2bfloat16(b);
    return (uint32_t)*reinterpret_cast<unsigned short*>(&h0) |
           ((uint32_t)*reinterpret_cast<unsigned short*>(&h1) << 16);
}

// ---------------------------------------------------------------------------
// Kernel 0: weight prep (fp16 split lrp, fp16 gate, bf16 og/op)
// ---------------------------------------------------------------------------
__global__ void k0_wprep(const float* __restrict__ lrpw, const float* __restrict__ gatew,
                         const float* __restrict__ ogw,  const float* __restrict__ opw)
{
    int i = blockIdx.x * blockDim.x + threadIdx.x;
    if (i < 256 * 128) {
        float v = lrpw[i];
        __half h = __float2half(v);
        g_Wl_h16[i] = h;
        g_Wl_l16[i] = __float2half(v - __half2float(h));
        g_Wg_16[i] = __float2half(gatew[i]);
    }
    if (i < 128 * 128) {
        g_Wo_bf[i] = __float2bfloat16(ogw[i]);
        g_Wp_bf[i] = __float2bfloat16(opw[i]);
    }
}

// ---------------------------------------------------------------------------
// Kernel 1 (fp16 HMMA): LN1 + lrp (2-prod) / gate (1-prod) -> fp16 L / R
// 64 rows/CTA, 4 c-tiles of 64 channels. smem: A 16KB | W 48KB (stage aliases)
// 64KB -> 3 CTAs/SM, 4096 CTAs
// ---------------------------------------------------------------------------
#define K1_A_OFF   0
#define K1_W_OFF   16384
#define K1_SMEM    65536

__global__ __launch_bounds__(256, 3)
void k1_mma(const float* __restrict__ Z, const float* __restrict__ mask,
            const float* __restrict__ ln1w, const float* __restrict__ ln1b,
            const float* __restrict__ lrpb, const float* __restrict__ gateb)
{
    extern __shared__ __align__(1024) char smc[];
    const uint32_t sbase = smem_u32(smc);
    uint32_t* stage = reinterpret_cast<uint32_t*>(smc + K1_W_OFF);   // aliases W planes

    const int tid = threadIdx.x;
    const int warp = tid >> 5;
    const uint32_t lane = tid & 31;
    const int r0 = blockIdx.x * 64;

    // ---- Phase A: load Z rows (8/warp), LN1, single fp16 plane (2 kc) ----
    {
        const int k4 = lane * 4;
        const int kc = lane >> 4;
        const uint32_t kb = (lane & 15) * 8;
        float4 w4 = *reinterpret_cast<const float4*>(ln1w + k4);
        float4 b4 = *reinterpret_cast<const float4*>(ln1b + k4);
        #pragma unroll 2
        for (int rr = 0; rr < 8; rr++) {
            int rloc = warp * 8 + rr;
            float4 v = *reinterpret_cast<const float4*>(Z + (size_t)(r0 + rloc) * DDIM + k4);
            float s  = v.x + v.y + v.z + v.w;
            float s2 = v.x * v.x + v.y * v.y + v.z * v.z + v.w * v.w;
            #pragma unroll
            for (int o = 16; o; o >>= 1) {
                s  += __shfl_xor_sync(0xffffffffu, s, o);
                s2 += __shfl_xor_sync(0xffffffffu, s2, o);
            }
            float m = s * 0.0078125f;
            float var = fmaf(-m, m, s2 * 0.0078125f);
            float rstd = rsqrtf(var + 1e-5f);
            float zn[4] = {
                (v.x - m) * rstd * w4.x + b4.x,
                (v.y - m) * rstd * w4.y + b4.y,
                (v.z - m) * rstd * w4.z + b4.z,
                (v.w - m) * rstd * w4.w + b4.w };
            uint32_t sw = sw128((uint32_t)(rloc * 128) + kb);
            *reinterpret_cast<uint2*>(smc + K1_A_OFF + kc * 8192 + sw) =
                make_uint2(pack_h2(zn[0], zn[1]), pack_h2(zn[2], zn[3]));
        }
    }
    __syncthreads();

    const int wm = (warp >> 1) * 16;     // 0..48
    const int wn = (warp & 1) * 32;      // 0/32 within 64-channel tile

    const uint32_t a_row = (lane & 7) + ((lane >> 3) & 1) * 8;
    const uint32_t a_kb  = (lane >> 4) * 16;
    const uint32_t b_row = (lane & 7) + ((lane >> 4) & 1) * 8;
    const uint32_t b_kb  = ((lane >> 3) & 1) * 16;

    const __half* wtab[3] = { g_Wl_h16, g_Wl_l16, g_Wg_16 };

    #pragma unroll 1
    for (int ct = 0; ct < 4; ct++) {
        const int cbase = ct * 64;

        // ---- load 6 W planes (3 mats x 2 kc), 64 rows x 128B each ----
        #pragma unroll
        for (int it = 0; it < 12; it++) {
            int u = it * 256 + tid;
            int p = u >> 9; int idx = u & 511;
            int row = idx >> 3, q = idx & 7;
            int shl = p >> 1, kc = p & 1;
            const __half* src = wtab[shl] + (size_t)(cbase + row) * 128 + kc * 64 + q * 8;
            cp16(sbase + K1_W_OFF + p * 8192 + sw128((uint32_t)(row * 128 + q * 16)), src);
        }
        CP_COMMIT();
        CP_WAIT0();
        __syncthreads();

        float accl[4][4], accg[4][4];
        #pragma unroll
        for (int nt = 0; nt < 4; nt++)
            #pragma unroll
            for (int q = 0; q < 4; q++) { accl[nt][q] = 0.f; accg[nt][q] = 0.f; }

        #pragma unroll
        for (int kc = 0; kc < 2; kc++) {
            #pragma unroll
            for (int ks = 0; ks < 4; ks++) {
                uint32_t kb = ks * 32;
                uint32_t a[4];
                uint32_t swa = sw128((uint32_t)((wm + a_row) * 128) + kb + a_kb);
                ldm_x4(a, sbase + K1_A_OFF + kc * 8192 + swa);
                #pragma unroll
                for (int ng = 0; ng < 2; ng++) {
                    uint32_t swb = sw128((uint32_t)((wn + ng * 16 + b_row) * 128) + kb + b_kb);
                    uint32_t wlh[4], wll[4], wg[4];
                    ldm_x4(wlh, sbase + K1_W_OFF + (0 + kc) * 8192 + swb);
                    ldm_x4(wll, sbase + K1_W_OFF + (2 + kc) * 8192 + swb);
                    ldm_x4(wg,  sbase + K1_W_OFF + (4 + kc) * 8192 + swb);
                    #pragma unroll
                    for (int h = 0; h < 2; h++) {
                        float* cl = accl[ng * 2 + h];
                        float* cg = accg[ng * 2 + h];
                        mma16816h(cl, a, wlh[h*2], wlh[h*2+1]);
                        mma16816h(cl, a, wll[h*2], wll[h*2+1]);
                        mma16816h(cg, a, wg[h*2],  wg[h*2+1]);
                    }
                }
            }
        }
        __syncthreads();   // all warps done reading W before stage (aliased) writes

        {
            int rl0 = wm + (int)(lane >> 2);
            float m0 = mask[r0 + rl0];
            float m1 = mask[r0 + rl0 + 8];
            #pragma unroll
            for (int nt = 0; nt < 4; nt++) {
                int cl0 = wn + nt * 8 + 2 * (int)(lane & 3);
                float lb0 = lrpb[cbase + cl0],  lb1 = lrpb[cbase + cl0 + 1];
                float gb0 = gateb[cbase + cl0], gb1 = gateb[cbase + cl0 + 1];
                float* vl = accl[nt];
                float* vg = accg[nt];
                stage[(cl0    ) * 68 + rl0    ] = pack_h1((vl[0] + lb0) * m0 * sigmoidf_(vg[0] + gb0));
                stage[(cl0 + 1) * 68 + rl0    ] = pack_h1((vl[1] + lb1) * m0 * sigmoidf_(vg[1] + gb1));
                stage[(cl0    ) * 68 + rl0 + 8] = pack_h1((vl[2] + lb0) * m1 * sigmoidf_(vg[2] + gb0));
                stage[(cl0 + 1) * 68 + rl0 + 8] = pack_h1((vl[3] + lb1) * m1 * sigmoidf_(vg[3] + gb1));
            }
        }
        __syncthreads();

        {
            int c_loc = tid >> 2;            // 0..63
            int seg = tid & 3;               // 4 segments of 16 rows
            int cg = cbase + c_loc;
            __half* dst = (cg < 128) ? (g_L16 + (size_t)cg * NN) : (g_R16 + (size_t)(cg - 128) * NN);
            int rb = seg * 16;
            const uint32_t* srow = &stage[c_loc * 68 + rb];
            #pragma unroll
            for (int blk = 0; blk < 2; blk++) {
                uint32_t hw[4];
                #pragma unroll
                for (int q = 0; q < 4; q++) {
                    uint32_t p0 = srow[blk * 8 + q * 2];
                    uint32_t p1 = srow[blk * 8 + q * 2 + 1];
                    hw[q] = (p0 & 0xffffu) | (p1 << 16);
                }
                *reinterpret_cast<uint4*>(dst + r0 + rb + blk * 8) = make_uint4(hw[0], hw[1], hw[2], hw[3]);
            }
        }
        __syncthreads();
    }
}

// ---------------------------------------------------------------------------
// Kernel 2: fp16 1-product mma.sync GEMM  T_c = L_c @ R_c^T
// CTA tile 128(i) x 64(j), K-chunk 64, 3-stage, 3 CTAs/SM.
// ---------------------------------------------------------------------------
#define K2_AP 16384
#define K2_BP 8192
#define K2_STG (K2_AP + K2_BP)       // 24576
#define K2_SMEM (3 * K2_STG)         // 73728

__device__ __forceinline__ void k2_prefetch(uint32_t sbase, int stage_i,
    const __half* A, const __half* B,
    int i0, int j0, int k0, int tid)
{
    uint32_t st = sbase + stage_i * K2_STG;
    #pragma unroll
    for (int it = 0; it < 4; it++) {
        int idx = it * 256 + tid;
        int r = idx >> 3, q = idx & 7;
        uint32_t sw = sw128((uint32_t)(r * 128 + q * 16));
        cp16(st + sw, A + (size_t)(i0 + r) * NDIM + k0 + q * 8);
    }
    #pragma unroll
    for (int it = 0; it < 2; it++) {
        int idx = it * 256 + tid;
        int r = idx >> 3, q = idx & 7;
        uint32_t sw = sw128((uint32_t)(r * 128 + q * 16));
        cp16(st + K2_AP + sw, B + (size_t)(j0 + r) * NDIM + k0 + q * 8);
    }
    CP_COMMIT();
}

__global__ __launch_bounds__(256, 3)
void k2_tri_mma()
{
    extern __shared__ __align__(1024) char smc[];
    const uint32_t sbase = smem_u32(smc);
    const int tid = threadIdx.x;
    const int warp = tid >> 5;
    const uint32_t lane = tid & 31;
    const int c = blockIdx.z;
    const int i0 = blockIdx.x * 128, j0 = blockIdx.y * 64;

    const __half* __restrict__ A = g_L16 + (size_t)c * NN;
    const __half* __restrict__ B = g_R16 + (size_t)c * NN;
    float* __restrict__ Tc = g_T + (size_t)c * NN;

    const int wm = (warp >> 1) * 32;
    const int wn = (warp & 1) * 32;

    const uint32_t a_row = (lane & 7) + ((lane >> 3) & 1) * 8;
    const uint32_t a_kb  = (lane >> 4) * 16;
    const uint32_t b_row = (lane & 7) + ((lane >> 4) & 1) * 8;
    const uint32_t b_kb  = ((lane >> 3) & 1) * 16;

    float acc[2][4][4];
    #pragma unroll
    for (int mt = 0; mt < 2; mt++)
        #pragma unroll
        for (int nt = 0; nt < 4; nt++)
            #pragma unroll
            for (int q = 0; q < 4; q++) acc[mt][nt][q] = 0.0f;

    k2_prefetch(sbase, 0, A, B, i0, j0, 0, tid);
    k2_prefetch(sbase, 1, A, B, i0, j0, 64, tid);

    #pragma unroll 1
    for (int ch = 0; ch < 8; ch++) {
        if (ch == 7) { CP_WAIT0(); } else { CP_WAIT1(); }
        __syncthreads();
        if (ch + 2 < 8)
            k2_prefetch(sbase, (ch + 2) % 3, A, B, i0, j0, (ch + 2) * 64, tid);

        uint32_t st = sbase + (ch % 3) * K2_STG;
        uint32_t sA = st, sB = st + K2_AP;

        #pragma unroll
        for (int ks = 0; ks < 4; ks++) {
            uint32_t kb = ks * 32;
            uint32_t a[2][4];
            #pragma unroll
            for (int mt = 0; mt < 2; mt++) {
                uint32_t sw = sw128((uint32_t)((wm + mt * 16 + a_row) * 128) + kb + a_kb);
                ldm_x4(a[mt], sA + sw);
            }
            #pragma unroll
            for (int ng = 0; ng < 2; ng++) {
                uint32_t sw = sw128((uint32_t)((wn + ng * 16 + b_row) * 128) + kb + b_kb);
                uint32_t b[4];
                ldm_x4(b, sB + sw);
                #pragma unroll
                for (int mt = 0; mt < 2; mt++) {
                    #pragma unroll
                    for (int h = 0; h < 2; h++) {
                        mma16816h(acc[mt][ng * 2 + h], a[mt], b[h * 2], b[h * 2 + 1]);
                    }
                }
            }
        }
        __syncthreads();
    }

    const int rbase = i0 + wm + (int)(lane >> 2);
    const int cbase = j0 + wn + 2 * (int)(lane & 3);
    #pragma unroll
    for (int mt = 0; mt < 2; mt++) {
        #pragma unroll
        for (int nt = 0; nt < 4; nt++) {
            float* cc = acc[mt][nt];
            int col = cbase + nt * 8;
            int r1 = rbase + mt * 16;
            *reinterpret_cast<float2*>(&Tc[(size_t)r1 * NDIM + col])       = make_float2(cc[0], cc[1]);
            *reinterpret_cast<float2*>(&Tc[(size_t)(r1 + 8) * NDIM + col]) = make_float2(cc[2], cc[3]);
        }
    }
}

// ---------------------------------------------------------------------------
// Kernel 3 (HMMA): 64 rows x 128 cols per CTA, two 64-col W passes, 2 CTAs/SM.
// ---------------------------------------------------------------------------
#define K3_T_OFF   0
#define K3_A_OFF   33792
#define K3_W_OFF   66560
#define K3_SMEM    99328

__device__ __forceinline__ void k3_loadW(uint32_t sbase, int ch0, int tid) {
    #pragma unroll
    for (int it = 0; it < 8; it++) {
        int u = it * 256 + tid;
        int p = u >> 9; int idx = u & 511;
        int row = idx >> 3, q = idx & 7;
        int pl = p >> 1, kc = p & 1;
        const __nv_bfloat16* src = (pl == 0 ? g_Wo_bf : g_Wp_bf) + (size_t)(ch0 + row) * 128 + kc * 64 + q * 8;
        cp16(sbase + K3_W_OFF + p * 8192 + sw128((uint32_t)(row * 128 + q * 16)), src);
    }
    CP_COMMIT();
}

__global__ __launch_bounds__(256, 2)
void k3_mma(const float* __restrict__ ogb, const float* __restrict__ ln2w,
            const float* __restrict__ ln2b, const float* __restrict__ outb,
            float* __restrict__ out)
{
    extern __shared__ __align__(1024) char smc[];
    const uint32_t sbase = smem_u32(smc);
    float* s_t = reinterpret_cast<float*>(smc + K3_T_OFF);   // [64][132]

    const int tid = threadIdx.x;
    const int warp = tid >> 5;
    const uint32_t lane = tid & 31;
    const int r0 = blockIdx.x * 64;

    k3_loadW(sbase, 0, tid);

    #pragma unroll
    for (int it = 0; it < 8; it++) {
        int u = it * 256 + tid;
        int cch = u >> 4;
        int q = u & 15;
        float4 v = *reinterpret_cast<const float4*>(g_T + (size_t)cch * NN + r0 + q * 4);
        s_t[(q * 4 + 0) * 132 + cch] = v.x;
        s_t[(q * 4 + 1) * 132 + cch] = v.y;
        s_t[(q * 4 + 2) * 132 + cch] = v.z;
        s_t[(q * 4 + 3) * 132 + cch] = v.w;
    }
    __syncthreads();

    {
        const int c4 = lane * 4;
        const int kc = lane >> 4;
        const uint32_t kb = (lane & 15) * 8;
        float4 w4 = *reinterpret_cast<const float4*>(ln2w + c4);
        float4 b4 = *reinterpret_cast<const float4*>(ln2b + c4);
        #pragma unroll 1
        for (int rr = 0; rr < 8; rr++) {
            int rloc = warp * 8 + rr;
            float4 v = *reinterpret_cast<float4*>(&s_t[rloc * 132 + c4]);
            float s  = v.x + v.y + v.z + v.w;
            float s2 = v.x * v.x + v.y * v.y + v.z * v.z + v.w * v.w;
            #pragma unroll
            for (int o = 16; o; o >>= 1) {
                s  += __shfl_xor_sync(0xffffffffu, s, o);
                s2 += __shfl_xor_sync(0xffffffffu, s2, o);
            }
            float m = s * 0.0078125f;
            float var = fmaf(-m, m, s2 * 0.0078125f);
            float rstd = rsqrtf(var + 1e-5f);
            float zn[4] = {
                (v.x - m) * rstd * w4.x + b4.x,
                (v.y - m) * rstd * w4.y + b4.y,
                (v.z - m) * rstd * w4.z + b4.z,
                (v.w - m) * rstd * w4.w + b4.w };
            uint32_t sw = sw128((uint32_t)(rloc * 128) + kb);
            *reinterpret_cast<uint2*>(smc + K3_A_OFF + (0*2 + kc) * 8192 + sw) =
                make_uint2(pack_bf2(v.x, v.y), pack_bf2(v.z, v.w));
            *reinterpret_cast<uint2*>(smc + K3_A_OFF + (1*2 + kc) * 8192 + sw) =
                make_uint2(pack_bf2(zn[0], zn[1]), pack_bf2(zn[2], zn[3]));
        }
    }

    const int wm = (warp >> 1) * 16;
    const int wn = (warp & 1) * 32;

    const uint32_t a_row = (lane & 7) + ((lane >> 3) & 1) * 8;
    const uint32_t a_kb  = (lane >> 4) * 16;
    const uint32_t b_row = (lane & 7) + ((lane >> 4) & 1) * 8;
    const uint32_t b_kb  = ((lane >> 3) & 1) * 16;

    #pragma unroll 1
    for (int hh = 0; hh < 2; hh++) {
        const int ch0 = hh * 64;
        CP_WAIT0();
        __syncthreads();

        float accg[4][4], accz[4][4];
        #pragma unroll
        for (int nt = 0; nt < 4; nt++)
            #pragma unroll
            for (int q = 0; q < 4; q++) { accg[nt][q] = 0.f; accz[nt][q] = 0.f; }

        #pragma unroll
        for (int kc = 0; kc < 2; kc++) {
            #pragma unroll
            for (int ks = 0; ks < 4; ks++) {
                uint32_t kb = ks * 32;
                uint32_t ag[4], az[4];
                uint32_t swa = sw128((uint32_t)((wm + a_row) * 128) + kb + a_kb);
                ldm_x4(ag, sbase + K3_A_OFF + (0*2 + kc) * 8192 + swa);
                ldm_x4(az, sbase + K3_A_OFF + (1*2 + kc) * 8192 + swa);
                #pragma unroll
                for (int ng = 0; ng < 2; ng++) {
                    uint32_t swb = sw128((uint32_t)((wn + ng * 16 + b_row) * 128) + kb + b_kb);
                    uint32_t wo[4], wp[4];
                    ldm_x4(wo, sbase + K3_W_OFF + (0*2 + kc) * 8192 + swb);
                    ldm_x4(wp, sbase + K3_W_OFF + (1*2 + kc) * 8192 + swb);
                    #pragma unroll
                    for (int h = 0; h < 2; h++) {
                        mma16816(accg[ng * 2 + h], ag, wo[h*2], wo[h*2+1]);
                        mma16816(accz[ng * 2 + h], az, wp[h*2], wp[h*2+1]);
                    }
                }
            }
        }
        __syncthreads();
        if (hh == 0) k3_loadW(sbase, 64, tid);

        {
            int rl0 = wm + (int)(lane >> 2);
            #pragma unroll
            for (int nt = 0; nt < 4; nt++) {
                int dl = wn + nt * 8 + 2 * (int)(lane & 3);
                int d = ch0 + dl;
                float ob0 = ogb[d],  ob1 = ogb[d + 1];
                float ub0 = outb[d], ub1 = outb[d + 1];
                float* cg = accg[nt];
                float* cz = accz[nt];
                float2 t0 = *reinterpret_cast<float2*>(&s_t[rl0 * 132 + d]);
                float2 t1 = *reinterpret_cast<float2*>(&s_t[(rl0 + 8) * 132 + d]);
                float2 o0, o1;
                o0.x = t0.x + sigmoidf_(cg[0] + ob0) * (cz[0] + ub0);
                o0.y = t0.y + sigmoidf_(cg[1] + ob1) * (cz[1] + ub1);
                o1.x = t1.x + sigmoidf_(cg[2] + ob0) * (cz[2] + ub0);
                o1.y = t1.y + sigmoidf_(cg[3] + ob1) * (cz[3] + ub1);
                *reinterpret_cast<float2*>(&out[(size_t)(r0 + rl0) * DDIM + d])     = o0;
                *reinterpret_cast<float2*>(&out[(size_t)(r0 + rl0 + 8) * DDIM + d]) = o1;
            }
        }
    }
}

// ---------------------------------------------------------------------------
extern "C" void kernel_launch(void* const* d_in, const int* in_sizes, int n_in,
                              void* d_out, int out_size)
{
    const float* Z     = (const float*)d_in[0];
    const float* mask  = (const float*)d_in[1];
    const float* ln1w  = (const float*)d_in[2];
    const float* ln1b  = (const float*)d_in[3];
    const float* lrpw  = (const float*)d_in[4];
    const float* lrpb  = (const float*)d_in[5];
    const float* gatew = (const float*)d_in[6];
    const float* gateb = (const float*)d_in[7];
    const float* ogw   = (const float*)d_in[8];
    const float* ogb   = (const float*)d_in[9];
    const float* ln2w  = (const float*)d_in[10];
    const float* ln2b  = (const float*)d_in[11];
    const float* opw   = (const float*)d_in[12];
    const float* outb  = (const float*)d_in[13];
    float* out = (float*)d_out;

    cudaFuncSetAttribute(k1_mma,     cudaFuncAttributeMaxDynamicSharedMemorySize, K1_SMEM);
    cudaFuncSetAttribute(k2_tri_mma, cudaFuncAttributeMaxDynamicSharedMemorySize, K2_SMEM);
    cudaFuncSetAttribute(k3_mma,     cudaFuncAttributeMaxDynamicSharedMemorySize, K3_SMEM);

    k0_wprep<<<128, 256>>>(lrpw, gatew, ogw, opw);

    k1_mma<<<NN / 64, 256, K1_SMEM>>>(Z, mask, ln1w, ln1b, lrpb, gateb);

    dim3 g2(4, 8, 128);
    k2_tri_mma<<<g2, 256, K2_SMEM>>>();

    k3_mma<<<NN / 64, 256, K3_SMEM>>>(ogb, ln2w, ln2b, outb, out);
}